// round 8
// baseline (speedup 1.0000x reference)
#include <cuda_runtime.h>
#include <math.h>

// ---------------------------------------------------------------------------
// SoftLabelLoss: loss = max( (1/B) * sum_i [ e[t_i] - dot(soft[t_i], x_i) + lse(x_i) ], 0 )
//   soft[t][c] = 0.8*(c==t) + 0.2*sim[t][c]/rowsum(sim[t]);  e[t] = sum soft*log(soft)
// v8: soft table stored as bf16x2 in smem (58KB) -> 2 blocks/SM -> occ ~100%.
// e[t] kept f32 (computed pre-rounding). Unroll-4 register pipeline,
// compile-time C addressing, deterministic fixed-point finalize.
// ---------------------------------------------------------------------------

#define FXSCALE 4294967296.0   // 2^32

__device__ unsigned long long g_sum  = 0ULL;
__device__ unsigned int       g_done = 0u;

// --- warp sum (butterfly; REDUX.f32 does not exist on sm_103) -------------------
__device__ __forceinline__ float warp_sum_f32(float v) {
    #pragma unroll
    for (int o = 16; o; o >>= 1) v += __shfl_xor_sync(0xffffffffu, v, o);
    return v;
}

// exact bf16 -> f32 (low / high half of a packed bf16x2)
__device__ __forceinline__ float blo(unsigned u) { return __uint_as_float(u << 16); }
__device__ __forceinline__ float bhi(unsigned u) { return __uint_as_float(u & 0xffff0000u); }

__device__ __forceinline__ unsigned pack_bf16x2(float a, float b) {
    unsigned r;
    asm("cvt.rn.bf16x2.f32 %0, %1, %2;" : "=r"(r) : "f"(b), "f"(a));  // b=hi, a=lo
    return r;
}

// --- deterministic fixed-point finalize -------------------------------------------
__device__ __forceinline__ void block_finalize(float acc, int lane, int warp,
                                               double* s_w, float* out, int B) {
    double d = (double)acc;
    #pragma unroll
    for (int o = 16; o; o >>= 1) d += __shfl_xor_sync(0xffffffffu, d, o);
    if (lane == 0) s_w[warp] = d;
    __syncthreads();
    if (warp == 0) {
        int nw = (blockDim.x + 31) >> 5;
        double v = (lane < nw) ? s_w[lane] : 0.0;
        #pragma unroll
        for (int o = 16; o; o >>= 1) v += __shfl_xor_sync(0xffffffffu, v, o);
        if (lane == 0) {
            long long q = __double2ll_rn(v * FXSCALE);
            atomicAdd(&g_sum, (unsigned long long)q);
            __threadfence();
            unsigned int tk = atomicAdd(&g_done, 1u);
            if (tk == gridDim.x - 1) {
                unsigned long long raw = atomicAdd(&g_sum, 0ULL);
                double loss = ((double)(long long)raw / FXSCALE) / (double)B;
                out[0] = (float)(loss > 0.0 ? loss : 0.0);
                g_sum  = 0ULL;
                g_done = 0u;
                __threadfence();
            }
        }
    }
}

// --- main kernel, compile-time C (C even, 128 < C <= 192) --------------------------
template<int C>
__global__ __launch_bounds__(1024, 2)
void slloss_v8(const float* __restrict__ logits,
               const int*   __restrict__ targets,
               const float* __restrict__ sim,
               float* __restrict__ out, int B) {
    constexpr int C2 = C / 2;                 // 85 bf16x2 words per table row
    static_assert((C & 1) == 0 && C2 > 64 && C2 <= 96, "tuned for 128<C<=192");

    extern __shared__ __align__(16) unsigned char smraw[];
    double*   s_w     = (double*)smraw;                          // 32 doubles (256B)
    float*    s_ent   = (float*)(smraw + 256);                   // C floats
    unsigned* s_softu = (unsigned*)(smraw + 256 + ((C * 4 + 15) & ~15)); // C*C2 words

    const int tid  = threadIdx.x;
    const int lane = tid & 31;
    const int warp = tid >> 5;

    // ---- build bf16 table + f32 entropies (warp t-rows; sim re-read from L1/L2) ----
    for (int t = warp; t < C; t += 32) {
        const float* srow = sim + (size_t)t * C;
        float s = 0.0f;
        for (int c = lane; c < C; c += 32) s += __ldg(srow + c);
        s = warp_sum_f32(s);
        const float inv = 0.2f / s;
        float p = 0.0f;
        for (int j = lane; j < C2; j += 32) {
            int c0 = 2 * j, c1 = 2 * j + 1;
            float v0 = __ldg(srow + c0) * inv + (c0 == t ? 0.8f : 0.0f);
            float v1 = __ldg(srow + c1) * inv + (c1 == t ? 0.8f : 0.0f);
            p += (v0 > 0.0f ? v0 * __logf(v0) : 0.0f)
               + (v1 > 0.0f ? v1 * __logf(v1) : 0.0f);
            s_softu[t * C2 + j] = pack_bf16x2(v0, v1);
        }
        p = warp_sum_f32(p);
        if (lane == 0) s_ent[t] = p;
    }
    __syncthreads();

    const int NW = gridDim.x * 32;
    const int gw = blockIdx.x * 32 + warp;

    long long per = ((long long)B + NW - 1) / NW;
    long long r0  = (long long)gw * per; if (r0 > B) r0 = B;
    long long r1  = r0 + per;            if (r1 > B) r1 = B;

    const bool act2 = lane < (C2 - 64);       // partial third chunk (lane < 21)

    float accD = 0.0f;   // -dot partials (all lanes)
    float accL = 0.0f;   // ent + log(se)  (lane 0 only)

    for (long long base = r0; base < r1; base += 32) {
        const int nrows  = (int)((r1 - base) < 32 ? (r1 - base) : 32);
        const int nrows4 = nrows & ~3;
        int t32 = (lane < nrows) ? __ldg(targets + base + lane) : 0;

        const float2* p = (const float2*)logits + base * C2;

        int r = 0;
        if (nrows4 >= 4) {
            float2 b0[3], b1[3], b2[3], b3[3];
            #define LD3(BUF, D)                                       \
                BUF[0] = __ldcs(p + (D) * C2 + lane);                 \
                BUF[1] = __ldcs(p + (D) * C2 + 32 + lane);            \
                if (act2) BUF[2] = __ldcs(p + (D) * C2 + 64 + lane);
            LD3(b0, 0) LD3(b1, 1) LD3(b2, 2) LD3(b3, 3)

            for (; r < nrows4; r += 4) {
                const bool more = (r + 4) < nrows4;

                #define DO_ROW(BUF, D)                                              \
                {                                                                   \
                    int t  = __shfl_sync(0xffffffffu, t32, r + (D));                \
                    int tw = (t >= 0) ? t : 0;                                      \
                    const unsigned* swu = s_softu + tw * C2;                        \
                    float2 x0 = BUF[0], x1 = BUF[1], x2 = BUF[2];                   \
                    if (more) { LD3(BUF, (D) + 4) }                                 \
                    unsigned wu0 = swu[lane], wu1 = swu[lane + 32];                 \
                    float se = __expf(x0.x) + __expf(x0.y)                          \
                             + __expf(x1.x) + __expf(x1.y);                         \
                    float dt = 0.0f;                                                \
                    dt = fmaf(blo(wu0), x0.x, dt); dt = fmaf(bhi(wu0), x0.y, dt);   \
                    dt = fmaf(blo(wu1), x1.x, dt); dt = fmaf(bhi(wu1), x1.y, dt);   \
                    if (act2) {                                                     \
                        unsigned wu2 = swu[lane + 64];                              \
                        se += __expf(x2.x) + __expf(x2.y);                          \
                        dt = fmaf(blo(wu2), x2.x, dt);                              \
                        dt = fmaf(bhi(wu2), x2.y, dt);                              \
                    }                                                               \
                    se = warp_sum_f32(se);                                          \
                    if (t >= 0) {                                                   \
                        accD -= dt;                                                 \
                        if (lane == 0) accL += s_ent[t] + __logf(se);               \
                    }                                                               \
                }

                DO_ROW(b0, 0)
                DO_ROW(b1, 1)
                DO_ROW(b2, 2)
                DO_ROW(b3, 3)
                #undef DO_ROW

                p += 4 * C2;
            }
            #undef LD3
        }

        // scalar tail (<4 rows; rare)
        for (; r < nrows; r++) {
            int t = __shfl_sync(0xffffffffu, t32, r);
            const float* lg = logits + (base + r) * (long long)C;
            const unsigned* swu = s_softu + ((t >= 0) ? t : 0) * C2;
            float se = 0.f, dt = 0.f;
            for (int j = lane; j < C2; j += 32) {
                float x0 = __ldg(lg + 2 * j), x1 = __ldg(lg + 2 * j + 1);
                unsigned wu = swu[j];
                se += __expf(x0) + __expf(x1);
                dt = fmaf(blo(wu), x0, dt);
                dt = fmaf(bhi(wu), x1, dt);
            }
            se = warp_sum_f32(se);
            if (t >= 0) {
                accD -= dt;
                if (lane == 0) accL += s_ent[t] + __logf(se);
            }
        }
    }

    block_finalize(accD + accL, lane, warp, s_w, out, B);
}

// --- generic fallback (any C, f32 table) ---------------------------------------------
__global__ __launch_bounds__(1024, 1)
void slloss_fused_gen(const float* __restrict__ logits,
                      const int*   __restrict__ targets,
                      const float* __restrict__ sim,
                      float* __restrict__ out,
                      int B, int C) {
    extern __shared__ float smemf[];
    float*  s_soft = smemf;
    float*  s_ent  = smemf + C * C;
    double* s_w    = (double*)(smemf + C * C + ((C + 1) & ~1));

    const int tid = threadIdx.x, lane = tid & 31, warp = tid >> 5;
    for (int t = warp; t < C; t += 32) {
        const float* srow = sim + (size_t)t * C;
        float s = 0.0f;
        for (int c = lane; c < C; c += 32) {
            float v = __ldg(srow + c);
            s_soft[t * C + c] = v;
            s += v;
        }
        s = warp_sum_f32(s);
        float inv = 0.2f / s;
        float p = 0.0f;
        for (int c = lane; c < C; c += 32) {
            float soft = s_soft[t * C + c] * inv + (c == t ? 0.8f : 0.0f);
            s_soft[t * C + c] = soft;
            p += (soft > 0.0f) ? soft * __logf(soft) : 0.0f;
        }
        p = warp_sum_f32(p);
        if (lane == 0) s_ent[t] = p;
    }
    __syncthreads();

    const int NW = gridDim.x * 32;
    const int gw = blockIdx.x * 32 + warp;
    long long per = ((long long)B + NW - 1) / NW;
    long long r0 = (long long)gw * per; if (r0 > B) r0 = B;
    long long r1 = r0 + per;            if (r1 > B) r1 = B;

    float acc = 0.0f;
    for (long long row = r0; row < r1; row++) {
        int t = __ldg(&targets[row]);
        if (t < 0) continue;
        const float* lg = logits + (size_t)row * C;
        const float* sw = s_soft + t * C;
        float se = 0.f, dt = 0.f;
        for (int c = lane; c < C; c += 32) {
            float x = __ldg(lg + c);
            se += __expf(x);
            dt = fmaf(sw[c], x, dt);
        }
        se = warp_sum_f32(se);
        acc -= dt;
        if (lane == 0) acc += s_ent[t] + __logf(se);
    }
    block_finalize(acc, lane, warp, s_w, out, B);
}

extern "C" void kernel_launch(void* const* d_in, const int* in_sizes, int n_in,
                              void* d_out, int out_size) {
    const float* logits  = (const float*)d_in[0];
    const int*   targets = (const int*)  d_in[1];
    const float* sim     = (const float*)d_in[2];
    float*       out     = (float*)d_out;

    int B = in_sizes[1];
    int C = in_sizes[0] / B;

    int nsm = 148;
    cudaDeviceGetAttribute(&nsm, cudaDevAttrMultiProcessorCount, 0);

    if (C == 170) {
        constexpr int Cc = 170, C2 = Cc / 2;
        size_t smem = 256 + ((Cc * 4 + 15) & ~15) + (size_t)Cc * C2 * 4;  // ~58.8KB
        cudaFuncSetAttribute(slloss_v8<Cc>, cudaFuncAttributeMaxDynamicSharedMemorySize, (int)smem);
        slloss_v8<Cc><<<2 * nsm, 1024, smem>>>(logits, targets, sim, out, B);
    } else {
        size_t smem = (size_t)(C * C + ((C + 1) & ~1)) * sizeof(float) + 32 * sizeof(double);
        cudaFuncSetAttribute(slloss_fused_gen, cudaFuncAttributeMaxDynamicSharedMemorySize, (int)smem);
        slloss_fused_gen<<<nsm, 1024, smem>>>(logits, targets, sim, out, B, C);
    }
}

// round 9
// speedup vs baseline: 1.1537x; 1.1537x over previous
#include <cuda_runtime.h>
#include <math.h>

// ---------------------------------------------------------------------------
// SoftLabelLoss: loss = max( (1/B) * sum_i [ e[t_i] - dot(soft[t_i], x_i) + lse(x_i) ], 0 )
//   soft[t][c] = 0.8*(c==t) + 0.2*sim[t][c]/rowsum(sim[t]);  e[t] = sum soft*log(soft)
// v9: per-warp cp.async (LDGSTS) smem ring (5 slots/warp), f32 table in smem,
// warp-per-row compute from smem, deterministic fixed-point finalize.
// ---------------------------------------------------------------------------

#define FXSCALE 4294967296.0   // 2^32

__device__ unsigned long long g_sum  = 0ULL;
__device__ unsigned int       g_done = 0u;

__device__ __forceinline__ float warp_sum_f32(float v) {
    #pragma unroll
    for (int o = 16; o; o >>= 1) v += __shfl_xor_sync(0xffffffffu, v, o);
    return v;
}

__device__ __forceinline__ unsigned smem_u32(const void* p) {
    unsigned r;
    asm("{ .reg .u64 t; cvta.to.shared.u64 t, %1; cvt.u32.u64 %0, t; }" : "=r"(r) : "l"(p));
    return r;
}
__device__ __forceinline__ void cp8(unsigned dst, const void* src) {
    asm volatile("cp.async.ca.shared.global [%0], [%1], 8;" :: "r"(dst), "l"(src) : "memory");
}
#define CP_COMMIT() asm volatile("cp.async.commit_group;" ::: "memory")
#define CP_WAIT3()  asm volatile("cp.async.wait_group 3;" ::: "memory")

// --- deterministic fixed-point finalize -------------------------------------------
__device__ __forceinline__ void block_finalize(float acc, int lane, int warp,
                                               double* s_w, float* out, int B) {
    double d = (double)acc;
    #pragma unroll
    for (int o = 16; o; o >>= 1) d += __shfl_xor_sync(0xffffffffu, d, o);
    if (lane == 0) s_w[warp] = d;
    __syncthreads();
    if (warp == 0) {
        int nw = (blockDim.x + 31) >> 5;
        double v = (lane < nw) ? s_w[lane] : 0.0;
        #pragma unroll
        for (int o = 16; o; o >>= 1) v += __shfl_xor_sync(0xffffffffu, v, o);
        if (lane == 0) {
            long long q = __double2ll_rn(v * FXSCALE);
            atomicAdd(&g_sum, (unsigned long long)q);
            __threadfence();
            unsigned int tk = atomicAdd(&g_done, 1u);
            if (tk == gridDim.x - 1) {
                unsigned long long raw = atomicAdd(&g_sum, 0ULL);
                double loss = ((double)(long long)raw / FXSCALE) / (double)B;
                out[0] = (float)(loss > 0.0 ? loss : 0.0);
                g_sum  = 0ULL;
                g_done = 0u;
                __threadfence();
            }
        }
    }
}

// --- shared f32 table build (warp-cooperative) --------------------------------------
__device__ __forceinline__ void build_table(const float* __restrict__ sim,
                                            float* s_soft, float* s_ent,
                                            int C, int lane, int warp) {
    for (int t = warp; t < C; t += 32) {
        const float* srow = sim + (size_t)t * C;
        float s = 0.0f;
        for (int c = lane; c < C; c += 32) {
            float v = __ldg(srow + c);
            s_soft[t * C + c] = v;
            s += v;
        }
        s = warp_sum_f32(s);
        float inv = 0.2f / s;
        float p = 0.0f;
        for (int c = lane; c < C; c += 32) {
            float soft = s_soft[t * C + c] * inv + (c == t ? 0.8f : 0.0f);
            s_soft[t * C + c] = soft;
            p += (soft > 0.0f) ? soft * __logf(soft) : 0.0f;
        }
        p = warp_sum_f32(p);
        if (lane == 0) s_ent[t] = p;
    }
}

// --- v9 main kernel, compile-time C (C even, 128 < C <= 172) -------------------------
template<int C>
__global__ __launch_bounds__(1024, 1)
void slloss_v9(const float* __restrict__ logits,
               const int*   __restrict__ targets,
               const float* __restrict__ sim,
               float* __restrict__ out, int B) {
    constexpr int C2    = C / 2;          // 85 float2 per row
    constexpr int DEPTH = 5;              // slots per warp
    constexpr int SLOTF = (C + 2 + 3) & ~3;  // slot stride in floats, 16B mult (172)
    static_assert((C & 1) == 0 && C2 > 64 && C2 <= 86, "tuned for 128<C<=172");

    extern __shared__ __align__(16) unsigned char smraw[];
    double* s_w    = (double*)smraw;                             // 256 B
    float*  s_ent  = (float*)(smraw + 256);                      // C floats (pad 688)
    float*  s_soft = (float*)(smraw + 256 + 688);                // C*C floats
    float*  s_slot = (float*)(smraw + 256 + 688 + C * C * 4);    // 32*DEPTH*SLOTF

    const int tid  = threadIdx.x;
    const int lane = tid & 31;
    const int warp = tid >> 5;

    build_table(sim, s_soft, s_ent, C, lane, warp);
    __syncthreads();

    const int NW = gridDim.x * 32;
    const int gw = blockIdx.x * 32 + warp;

    long long per = ((long long)B + NW - 1) / NW;
    long long r0  = (long long)gw * per; if (r0 > B) r0 = B;
    long long r1  = r0 + per;            if (r1 > B) r1 = B;
    const long long n = r1 - r0;

    const bool     act2   = lane < (C2 - 64);   // third chunk (lane < 21)
    float*         myslot = s_slot + warp * (DEPTH * SLOTF);
    const unsigned dst0   = smem_u32(myslot) + (unsigned)lane * 8u;

    float accD = 0.0f;   // -dot partials (all lanes)
    float accL = 0.0f;   // ent + log(se)  (lane 0 only)

    // prologue: rows r0..r0+2 as 3 groups (predicated loads, unconditional commits)
    #pragma unroll
    for (int k = 0; k < 3; k++) {
        if (k < n) {
            unsigned d = dst0 + (unsigned)k * (SLOTF * 4);
            const float2* s = (const float2*)logits + (r0 + k) * C2 + lane;
            cp8(d, s); cp8(d + 256, s + 32);
            if (act2) cp8(d + 512, s + 64);
        }
        CP_COMMIT();
    }

    int t32 = 0;
    int slotC = 0;                 // compute slot (i % DEPTH)
    int slotP = 3;                 // prefetch slot ((i+3) % DEPTH)

    for (long long i = 0; i < n; i++) {
        const int ib = (int)i & 31;
        if (ib == 0) {
            long long rem = n - i;
            t32 = (lane < rem) ? __ldg(targets + r0 + i + lane) : -1;
        }

        // issue row i+3 into slotP; always commit one group
        if (i + 3 < n) {
            unsigned d = dst0 + (unsigned)slotP * (SLOTF * 4);
            const float2* s = (const float2*)logits + (r0 + i + 3) * C2 + lane;
            cp8(d, s); cp8(d + 256, s + 32);
            if (act2) cp8(d + 512, s + 64);
        }
        CP_COMMIT();
        CP_WAIT3();                // row i's group (3 back) is now complete

        const float2* xp = (const float2*)(myslot + slotC * SLOTF);
        float2 x0 = xp[lane];
        float2 x1 = xp[lane + 32];

        int t  = __shfl_sync(0xffffffffu, t32, ib);
        int tw = (t >= 0) ? t : 0;
        const float2* sw = (const float2*)(s_soft + tw * C);

        float2 w0 = sw[lane], w1 = sw[lane + 32];
        float se = __expf(x0.x) + __expf(x0.y) + __expf(x1.x) + __expf(x1.y);
        float dt = 0.0f;
        dt = fmaf(w0.x, x0.x, dt); dt = fmaf(w0.y, x0.y, dt);
        dt = fmaf(w1.x, x1.x, dt); dt = fmaf(w1.y, x1.y, dt);
        if (act2) {
            float2 x2 = xp[lane + 64];
            float2 w2 = sw[lane + 64];
            se += __expf(x2.x) + __expf(x2.y);
            dt = fmaf(w2.x, x2.x, dt); dt = fmaf(w2.y, x2.y, dt);
        }
        se = warp_sum_f32(se);

        if (t >= 0) {
            accD -= dt;
            if (lane == 0) accL += s_ent[t] + __logf(se);
        }

        slotC = (slotC + 1 == DEPTH) ? 0 : slotC + 1;
        slotP = (slotP + 1 == DEPTH) ? 0 : slotP + 1;
    }

    block_finalize(accD + accL, lane, warp, s_w, out, B);
}

// --- generic fallback (any C, f32 table) ---------------------------------------------
__global__ __launch_bounds__(1024, 1)
void slloss_fused_gen(const float* __restrict__ logits,
                      const int*   __restrict__ targets,
                      const float* __restrict__ sim,
                      float* __restrict__ out,
                      int B, int C) {
    extern __shared__ float smemf[];
    float*  s_soft = smemf;
    float*  s_ent  = smemf + C * C;
    double* s_w    = (double*)(smemf + C * C + ((C + 1) & ~1));

    const int tid = threadIdx.x, lane = tid & 31, warp = tid >> 5;
    build_table(sim, s_soft, s_ent, C, lane, warp);
    __syncthreads();

    const int NW = gridDim.x * 32;
    const int gw = blockIdx.x * 32 + warp;
    long long per = ((long long)B + NW - 1) / NW;
    long long r0 = (long long)gw * per; if (r0 > B) r0 = B;
    long long r1 = r0 + per;            if (r1 > B) r1 = B;

    float acc = 0.0f;
    for (long long row = r0; row < r1; row++) {
        int t = __ldg(&targets[row]);
        if (t < 0) continue;
        const float* lg = logits + (size_t)row * C;
        const float* sw = s_soft + t * C;
        float se = 0.f, dt = 0.f;
        for (int c = lane; c < C; c += 32) {
            float x = __ldg(lg + c);
            se += __expf(x);
            dt = fmaf(sw[c], x, dt);
        }
        se = warp_sum_f32(se);
        acc -= dt;
        if (lane == 0) acc += s_ent[t] + __logf(se);
    }
    block_finalize(acc, lane, warp, s_w, out, B);
}

extern "C" void kernel_launch(void* const* d_in, const int* in_sizes, int n_in,
                              void* d_out, int out_size) {
    const float* logits  = (const float*)d_in[0];
    const int*   targets = (const int*)  d_in[1];
    const float* sim     = (const float*)d_in[2];
    float*       out     = (float*)d_out;

    int B = in_sizes[1];
    int C = in_sizes[0] / B;

    int nsm = 148;
    cudaDeviceGetAttribute(&nsm, cudaDevAttrMultiProcessorCount, 0);

    if (C == 170) {
        constexpr int Cc = 170, DEPTH = 5, SLOTF = (Cc + 2 + 3) & ~3;
        size_t smem = 256 + 688 + (size_t)Cc * Cc * 4 + (size_t)32 * DEPTH * SLOTF * 4;
        cudaFuncSetAttribute(slloss_v9<Cc>, cudaFuncAttributeMaxDynamicSharedMemorySize, (int)smem);
        slloss_v9<Cc><<<nsm, 1024, smem>>>(logits, targets, sim, out, B);
    } else {
        size_t smem = (size_t)(C * C + ((C + 1) & ~1)) * sizeof(float) + 32 * sizeof(double);
        cudaFuncSetAttribute(slloss_fused_gen, cudaFuncAttributeMaxDynamicSharedMemorySize, (int)smem);
        slloss_fused_gen<<<nsm, 1024, smem>>>(logits, targets, sim, out, B, C);
    }
}

// round 10
// speedup vs baseline: 1.7141x; 1.4857x over previous
#include <cuda_runtime.h>
#include <math.h>

// ---------------------------------------------------------------------------
// SoftLabelLoss: loss = max( (1/B) * sum_i [ e[t_i] - dot(soft[t_i], x_i) + lse(x_i) ], 0 )
//   soft[t][c] = 0.8*(c==t) + 0.2*sim[t][c]/rowsum(sim[t]);  e[t] = sum soft*log(soft)
// v10: R4 register pipeline + batched lse reduction via smem (no per-row
// shuffle butterfly / logf). f32 table in smem, fixed-point finalize.
// ---------------------------------------------------------------------------

#define FXSCALE 4294967296.0   // 2^32

__device__ unsigned long long g_sum  = 0ULL;
__device__ unsigned int       g_done = 0u;

__device__ __forceinline__ float warp_sum_f32(float v) {
    #pragma unroll
    for (int o = 16; o; o >>= 1) v += __shfl_xor_sync(0xffffffffu, v, o);
    return v;
}

// --- deterministic fixed-point finalize -------------------------------------------
__device__ __forceinline__ void block_finalize(float acc, int lane, int warp,
                                               double* s_w, float* out, int B) {
    double d = (double)acc;
    #pragma unroll
    for (int o = 16; o; o >>= 1) d += __shfl_xor_sync(0xffffffffu, d, o);
    if (lane == 0) s_w[warp] = d;
    __syncthreads();
    if (warp == 0) {
        int nw = (blockDim.x + 31) >> 5;
        double v = (lane < nw) ? s_w[lane] : 0.0;
        #pragma unroll
        for (int o = 16; o; o >>= 1) v += __shfl_xor_sync(0xffffffffu, v, o);
        if (lane == 0) {
            long long q = __double2ll_rn(v * FXSCALE);
            atomicAdd(&g_sum, (unsigned long long)q);
            __threadfence();
            unsigned int tk = atomicAdd(&g_done, 1u);
            if (tk == gridDim.x - 1) {
                unsigned long long raw = atomicAdd(&g_sum, 0ULL);
                double loss = ((double)(long long)raw / FXSCALE) / (double)B;
                out[0] = (float)(loss > 0.0 ? loss : 0.0);
                g_sum  = 0ULL;
                g_done = 0u;
                __threadfence();
            }
        }
    }
}

// --- shared f32 table build (warp-cooperative) --------------------------------------
__device__ __forceinline__ void build_table(const float* __restrict__ sim,
                                            float* s_soft, float* s_ent,
                                            int C, int lane, int warp) {
    for (int t = warp; t < C; t += 32) {
        const float* srow = sim + (size_t)t * C;
        float s = 0.0f;
        for (int c = lane; c < C; c += 32) {
            float v = __ldg(srow + c);
            s_soft[t * C + c] = v;
            s += v;
        }
        s = warp_sum_f32(s);
        float inv = 0.2f / s;
        float p = 0.0f;
        for (int c = lane; c < C; c += 32) {
            float soft = s_soft[t * C + c] * inv + (c == t ? 0.8f : 0.0f);
            s_soft[t * C + c] = soft;
            p += (soft > 0.0f) ? soft * __logf(soft) : 0.0f;
        }
        p = warp_sum_f32(p);
        if (lane == 0) s_ent[t] = p;
    }
}

// --- v10 main kernel, compile-time C (C even, 128 < C <= 172) ------------------------
template<int C>
__global__ __launch_bounds__(1024, 1)
void slloss_v10(const float* __restrict__ logits,
                const int*   __restrict__ targets,
                const float* __restrict__ sim,
                float* __restrict__ out, int B) {
    constexpr int C2   = C / 2;         // 85 float2 per row
    constexpr int RSTR = 36;            // se-partial row stride (floats), 16B mult
    static_assert((C & 1) == 0 && C2 > 64 && C2 <= 86, "tuned for 128<C<=172");

    extern __shared__ __align__(16) unsigned char smraw[];
    double* s_w    = (double*)smraw;                              // 256 B
    float*  s_ent  = (float*)(smraw + 256);                       // C floats (pad 688)
    float*  s_soft = (float*)(smraw + 256 + 688);                 // C*C floats
    float*  s_red  = (float*)(smraw + 256 + 688 + C * C * 4);     // 32*16*RSTR floats

    const int tid  = threadIdx.x;
    const int lane = tid & 31;
    const int warp = tid >> 5;

    build_table(sim, s_soft, s_ent, C, lane, warp);
    __syncthreads();

    const int NW = gridDim.x * 32;
    const int gw = blockIdx.x * 32 + warp;

    long long per = (((long long)B + NW - 1) / NW + 15) & ~15LL;  // mult of 16
    long long r0  = (long long)gw * per; if (r0 > B) r0 = B;
    long long r1  = r0 + per;            if (r1 > B) r1 = B;
    const long long n   = r1 - r0;
    const long long n16 = n & ~15LL;

    const bool act2 = lane < (C2 - 64);       // partial third chunk (lane < 21)
    float* red = s_red + warp * (16 * RSTR);

    float accD = 0.0f;   // -dot partials (all lanes)
    float accL = 0.0f;   // ent + log(se)  (lanes 0..15 in batched mode)

    int t32 = -1;

    if (n16 >= 16) {
        const float2* p = (const float2*)logits + r0 * C2;

        float2 b0[3], b1[3], b2[3], b3[3];
        #define LD3(BUF, D)                                       \
            BUF[0] = __ldcs(p + (D) * C2 + lane);                 \
            BUF[1] = __ldcs(p + (D) * C2 + 32 + lane);            \
            if (act2) BUF[2] = __ldcs(p + (D) * C2 + 64 + lane);
        LD3(b0, 0) LD3(b1, 1) LD3(b2, 2) LD3(b3, 3)

        for (long long g = 0; g * 16 < n16; g++) {
            const int gp = (int)g & 1;
            if (gp == 0) {
                long long rem = n - g * 16;
                t32 = (lane < rem) ? __ldg(targets + r0 + g * 16 + lane) : -1;
            }
            const int sidx = gp << 4;

            #pragma unroll
            for (int rr = 0; rr < 16; rr += 4) {
                const bool more = (g * 16 + rr + 4) < n16;

                #define DO_ROW(BUF, D)                                              \
                {                                                                   \
                    int t  = __shfl_sync(0xffffffffu, t32, sidx + rr + (D));        \
                    int tw = (t >= 0) ? t : 0;                                      \
                    const float2* sw = (const float2*)(s_soft + tw * C);            \
                    float2 x0 = BUF[0], x1 = BUF[1], x2 = BUF[2];                   \
                    if (more) { LD3(BUF, (D) + 4) }                                 \
                    float2 w0 = sw[lane], w1 = sw[lane + 32];                       \
                    float se = __expf(x0.x) + __expf(x0.y)                          \
                             + __expf(x1.x) + __expf(x1.y);                         \
                    float dt = 0.0f;                                                \
                    dt = fmaf(w0.x, x0.x, dt); dt = fmaf(w0.y, x0.y, dt);           \
                    dt = fmaf(w1.x, x1.x, dt); dt = fmaf(w1.y, x1.y, dt);           \
                    if (act2) {                                                     \
                        float2 w2 = sw[lane + 64];                                  \
                        se += __expf(x2.x) + __expf(x2.y);                          \
                        dt = fmaf(w2.x, x2.x, dt); dt = fmaf(w2.y, x2.y, dt);       \
                    }                                                               \
                    red[(rr + (D)) * RSTR + lane] = se;                             \
                    if (t >= 0) accD -= dt;                                         \
                }

                DO_ROW(b0, 0)
                DO_ROW(b1, 1)
                DO_ROW(b2, 2)
                DO_ROW(b3, 3)
                #undef DO_ROW

                p += 4 * C2;
            }

            // batched lse: lanes 0..15 each own one row of this 16-row group
            __syncwarp();
            float sum = 0.0f;
            if (lane < 16) {
                const float4* q = (const float4*)(red + lane * RSTR);
                #pragma unroll
                for (int k = 0; k < 8; k++) {
                    float4 v = q[k];
                    sum += (v.x + v.y) + (v.z + v.w);
                }
            }
            int tr = __shfl_sync(0xffffffffu, t32, (sidx + lane) & 31);
            if (lane < 16 && tr >= 0) accL += s_ent[tr] + __logf(sum);
            __syncwarp();
        }
        #undef LD3
    }

    // scalar tail (<16 rows; empty when B is a multiple of 16)
    for (long long i = n16; i < n; i++) {
        int t = __ldg(targets + r0 + i);
        const float* lg = logits + (r0 + i) * (long long)C;
        const float* sw = s_soft + ((t >= 0) ? t : 0) * C;
        float se = 0.f, dt = 0.f;
        for (int c = lane; c < C; c += 32) {
            float x = __ldg(lg + c);
            se += __expf(x);
            dt = fmaf(sw[c], x, dt);
        }
        se = warp_sum_f32(se);
        if (t >= 0) {
            accD -= dt;
            if (lane == 0) accL += s_ent[t] + __logf(se);
        }
    }

    block_finalize(accD + accL, lane, warp, s_w, out, B);
}

// --- generic fallback (any C, f32 table) ---------------------------------------------
__global__ __launch_bounds__(1024, 1)
void slloss_fused_gen(const float* __restrict__ logits,
                      const int*   __restrict__ targets,
                      const float* __restrict__ sim,
                      float* __restrict__ out,
                      int B, int C) {
    extern __shared__ float smemf[];
    float*  s_soft = smemf;
    float*  s_ent  = smemf + C * C;
    double* s_w    = (double*)(smemf + C * C + ((C + 1) & ~1));

    const int tid = threadIdx.x, lane = tid & 31, warp = tid >> 5;
    build_table(sim, s_soft, s_ent, C, lane, warp);
    __syncthreads();

    const int NW = gridDim.x * 32;
    const int gw = blockIdx.x * 32 + warp;
    long long per = ((long long)B + NW - 1) / NW;
    long long r0 = (long long)gw * per; if (r0 > B) r0 = B;
    long long r1 = r0 + per;            if (r1 > B) r1 = B;

    float acc = 0.0f;
    for (long long row = r0; row < r1; row++) {
        int t = __ldg(&targets[row]);
        if (t < 0) continue;
        const float* lg = logits + (size_t)row * C;
        const float* sw = s_soft + t * C;
        float se = 0.f, dt = 0.f;
        for (int c = lane; c < C; c += 32) {
            float x = __ldg(lg + c);
            se += __expf(x);
            dt = fmaf(sw[c], x, dt);
        }
        se = warp_sum_f32(se);
        acc -= dt;
        if (lane == 0) acc += s_ent[t] + __logf(se);
    }
    block_finalize(acc, lane, warp, s_w, out, B);
}

extern "C" void kernel_launch(void* const* d_in, const int* in_sizes, int n_in,
                              void* d_out, int out_size) {
    const float* logits  = (const float*)d_in[0];
    const int*   targets = (const int*)  d_in[1];
    const float* sim     = (const float*)d_in[2];
    float*       out     = (float*)d_out;

    int B = in_sizes[1];
    int C = in_sizes[0] / B;

    int nsm = 148;
    cudaDeviceGetAttribute(&nsm, cudaDevAttrMultiProcessorCount, 0);

    if (C == 170) {
        constexpr int Cc = 170;
        size_t smem = 256 + 688 + (size_t)Cc * Cc * 4 + (size_t)32 * 16 * 36 * 4;
        cudaFuncSetAttribute(slloss_v10<Cc>, cudaFuncAttributeMaxDynamicSharedMemorySize, (int)smem);
        slloss_v10<Cc><<<nsm, 1024, smem>>>(logits, targets, sim, out, B);
    } else {
        size_t smem = (size_t)(C * C + ((C + 1) & ~1)) * sizeof(float) + 32 * sizeof(double);
        cudaFuncSetAttribute(slloss_fused_gen, cudaFuncAttributeMaxDynamicSharedMemorySize, (int)smem);
        slloss_fused_gen<<<nsm, 1024, smem>>>(logits, targets, sim, out, B, C);
    }
}